// round 6
// baseline (speedup 1.0000x reference)
#include <cuda_runtime.h>
#include <cuda_bf16.h>
#include <cstdint>

#define BATCH 8
#define SLEN 1024
#define DMODEL 1024
#define NHEADS 16
#define HDIM 64
#define MROWS (BATCH * SLEN)       // 8192
#define QKV_N (3 * DMODEL)         // 3072
#define LN_EPS 1e-5f
#define SM_SCALE 0.03125f          // 1/sqrt(1024)

typedef __nv_bfloat16 bf;

// Scratch (static device globals: allocation-free rule)
__device__ bf g_xhi[(size_t)MROWS * DMODEL];
__device__ bf g_xlo[(size_t)MROWS * DMODEL];
__device__ bf g_wqkv_hi[(size_t)DMODEL * QKV_N];
__device__ bf g_wqkv_lo[(size_t)DMODEL * QKV_N];
__device__ bf g_wout_hi[(size_t)DMODEL * DMODEL];
__device__ bf g_wout_lo[(size_t)DMODEL * DMODEL];
__device__ bf g_qkv_hi[(size_t)MROWS * QKV_N];
__device__ bf g_qkv_lo[(size_t)MROWS * QKV_N];
__device__ bf g_attn_hi[(size_t)MROWS * DMODEL];
__device__ bf g_attn_lo[(size_t)MROWS * DMODEL];

// ---------------------------------------------------------------------------
// helpers
// ---------------------------------------------------------------------------
__device__ __forceinline__ uint32_t cvta_smem(const void* p) {
    uint32_t a;
    asm("{.reg .u64 t; cvta.to.shared.u64 t, %1; cvt.u32.u64 %0, t;}"
        : "=r"(a) : "l"(p));
    return a;
}
__device__ __forceinline__ void ldsm4(uint32_t a, uint32_t& r0, uint32_t& r1,
                                      uint32_t& r2, uint32_t& r3) {
    asm volatile("ldmatrix.sync.aligned.m8n8.x4.shared.b16 {%0,%1,%2,%3},[%4];"
                 : "=r"(r0), "=r"(r1), "=r"(r2), "=r"(r3) : "r"(a));
}
__device__ __forceinline__ void ldsm4t(uint32_t a, uint32_t& r0, uint32_t& r1,
                                       uint32_t& r2, uint32_t& r3) {
    asm volatile("ldmatrix.sync.aligned.m8n8.x4.trans.shared.b16 {%0,%1,%2,%3},[%4];"
                 : "=r"(r0), "=r"(r1), "=r"(r2), "=r"(r3) : "r"(a));
}
__device__ __forceinline__ void mma_bf16(float* c, const uint32_t* a,
                                         const uint32_t* b) {
    asm volatile(
        "mma.sync.aligned.m16n8k16.row.col.f32.bf16.bf16.f32 "
        "{%0,%1,%2,%3},{%4,%5,%6,%7},{%8,%9},{%0,%1,%2,%3};"
        : "+f"(c[0]), "+f"(c[1]), "+f"(c[2]), "+f"(c[3])
        : "r"(a[0]), "r"(a[1]), "r"(a[2]), "r"(a[3]), "r"(b[0]), "r"(b[1]));
}
__device__ __forceinline__ void split2(float x, float y, uint32_t& hi,
                                       uint32_t& lo) {
    bf hx = __float2bfloat16(x), hy = __float2bfloat16(y);
    bf lx = __float2bfloat16(x - __bfloat162float(hx));
    bf ly = __float2bfloat16(y - __bfloat162float(hy));
    __nv_bfloat162 h = __halves2bfloat162(hx, hy);
    __nv_bfloat162 l = __halves2bfloat162(lx, ly);
    hi = *(uint32_t*)&h;
    lo = *(uint32_t*)&l;
}
__device__ __forceinline__ void cp16(uint32_t s, const void* g) {
    asm volatile("cp.async.cg.shared.global [%0], [%1], 16;"
                 :: "r"(s), "l"(g));
}
#define CP_COMMIT() asm volatile("cp.async.commit_group;" ::: "memory")
#define CP_WAIT1()  asm volatile("cp.async.wait_group 1;" ::: "memory")

// ---------------------------------------------------------------------------
// fp32 -> (bf16 hi, bf16 lo) split conversion, vectorized by 4
// ---------------------------------------------------------------------------
__global__ __launch_bounds__(256) void cvt_kernel(
    const float4* __restrict__ in, uint2* __restrict__ hi,
    uint2* __restrict__ lo, int n4)
{
    int i = blockIdx.x * blockDim.x + threadIdx.x;
    if (i >= n4) return;
    float4 v = in[i];
    uint2 ho, loo;
    split2(v.x, v.y, ho.x, loo.x);
    split2(v.z, v.w, ho.y, loo.y);
    hi[i] = ho;
    lo[i] = loo;
}

// ---------------------------------------------------------------------------
// Tensor-core GEMM, bf16x2-split inputs, cp.async 3-stage pipeline
// (1 sync/iter, no register round-trip for staging).
// BM=BN=128, BK=32, 8 warps (64x32 warp tiles).
// ---------------------------------------------------------------------------
#define BM 128
#define BN 128
#define BK 32
#define A_STR 56        // BK + 24 pad: 112B rows, 16B-aligned, LDSM conflict-free
#define B_STR 136       // BN + 8 pad: 272B rows, 16B-aligned, conflict-free
#define ABUF (BM * A_STR)                 // 7168 elems per hi/lo
#define BBUF (BK * B_STR)                 // 4352 elems per hi/lo
#define GBUF_ELEMS (2 * ABUF + 2 * BBUF)  // 23040 elems = 46080 B / stage
#define GBUF_BYTES (GBUF_ELEMS * 2)
#define NSTAGE 3
#define GSMEM_BYTES (NSTAGE * GBUF_BYTES) // 138,240 B

template <bool RESID, bool SPLIT>
__global__ __launch_bounds__(256, 1) void mma_gemm(
    const bf* __restrict__ Ahi, const bf* __restrict__ Alo,
    const bf* __restrict__ Bhi, const bf* __restrict__ Blo,
    const float* __restrict__ bias, const float* __restrict__ res,
    float* __restrict__ C, bf* __restrict__ Chi, bf* __restrict__ Clo,
    int M, int N, int K)
{
    extern __shared__ __align__(16) bf dsm[];

    const int tid = threadIdx.x;
    const int lane = tid & 31;
    const int warp = tid >> 5;
    const int wm = warp >> 2;
    const int wn = warp & 3;
    const int bm0 = blockIdx.y * BM;
    const int bn0 = blockIdx.x * BN;

    const int ar = tid >> 2;          // 0..63 (rows ar, ar+64)
    const int ac = (tid & 3) * 8;     // k offset
    const int br = tid >> 3;          // 0..31
    const int bc = (tid & 7) * 16;    // n offset

    float acc[4][4][4];
    #pragma unroll
    for (int i = 0; i < 4; i++)
        #pragma unroll
        for (int j = 0; j < 4; j++)
            #pragma unroll
            for (int c = 0; c < 4; c++) acc[i][j][c] = 0.0f;

    const bf* Ah = Ahi + (size_t)(bm0 + ar) * K + ac;
    const bf* Al = Alo + (size_t)(bm0 + ar) * K + ac;
    const bf* Bh = Bhi + (size_t)br * N + bn0 + bc;
    const bf* Bl = Blo + (size_t)br * N + bn0 + bc;

    const uint32_t smb = cvta_smem(dsm);
    // per-thread staging offsets within one stage buffer (bytes)
    const uint32_t oAh0 = (ar * A_STR + ac) * 2;
    const uint32_t oAh1 = ((ar + 64) * A_STR + ac) * 2;
    const uint32_t oAl0 = ABUF * 2 + oAh0;
    const uint32_t oAl1 = ABUF * 2 + oAh1;
    const uint32_t oBh0 = 4 * ABUF + (br * B_STR + bc) * 2;
    const uint32_t oBh1 = oBh0 + 16;
    const uint32_t oBl0 = oBh0 + BBUF * 2;
    const uint32_t oBl1 = oBl0 + 16;

    const int iters = K / BK;

    auto stage = [&](int it) {
        const uint32_t sb = smb + (uint32_t)(it % NSTAGE) * GBUF_BYTES;
        const size_t ka = (size_t)it * BK;
        cp16(sb + oAh0, Ah + ka);
        cp16(sb + oAh1, Ah + (size_t)64 * K + ka);
        cp16(sb + oAl0, Al + ka);
        cp16(sb + oAl1, Al + (size_t)64 * K + ka);
        const size_t kb = ka * N;
        cp16(sb + oBh0, Bh + kb);
        cp16(sb + oBh1, Bh + kb + 8);
        cp16(sb + oBl0, Bl + kb);
        cp16(sb + oBl1, Bl + kb + 8);
        CP_COMMIT();
    };

    stage(0);
    stage(1);

    for (int it = 0; it < iters; it++) {
        CP_WAIT1();          // stage 'it' landed
        __syncthreads();     // visible CTA-wide; also fences buffer reuse

        const uint32_t bufa = smb + (uint32_t)(it % NSTAGE) * GBUF_BYTES;
        const uint32_t aAh = bufa;
        const uint32_t aAl = bufa + ABUF * 2;
        const uint32_t aBh = bufa + 4 * ABUF;
        const uint32_t aBl = aBh + BBUF * 2;

        #pragma unroll
        for (int kk = 0; kk < 2; kk++) {
            uint32_t ah[4][4], al[4][4], bh[4][2], bl[4][2];
            const int arow = wm * 64 + (lane & 15);
            const int acol = kk * 16 + (lane >> 4) * 8;
            #pragma unroll
            for (int mt = 0; mt < 4; mt++) {
                const uint32_t off = ((arow + mt * 16) * A_STR + acol) * 2;
                ldsm4(aAh + off, ah[mt][0], ah[mt][1], ah[mt][2], ah[mt][3]);
                ldsm4(aAl + off, al[mt][0], al[mt][1], al[mt][2], al[mt][3]);
            }
            const int brow = kk * 16 + (lane & 15);
            #pragma unroll
            for (int ng = 0; ng < 2; ng++) {
                const int bcol = wn * 32 + ng * 16 + (lane >> 4) * 8;
                const uint32_t off = (brow * B_STR + bcol) * 2;
                ldsm4t(aBh + off,
                       bh[2*ng][0], bh[2*ng][1], bh[2*ng+1][0], bh[2*ng+1][1]);
                ldsm4t(aBl + off,
                       bl[2*ng][0], bl[2*ng][1], bl[2*ng+1][0], bl[2*ng+1][1]);
            }
            #pragma unroll
            for (int mt = 0; mt < 4; mt++)
                #pragma unroll
                for (int nt = 0; nt < 4; nt++) {
                    mma_bf16(acc[mt][nt], ah[mt], bh[nt]);
                    mma_bf16(acc[mt][nt], ah[mt], bl[nt]);
                    mma_bf16(acc[mt][nt], al[mt], bh[nt]);
                }
        }

        // issue stage it+2 AFTER compute: targets buf[(it+2)%3], distinct from
        // the buffer any warp can be reading between this iter's barrier and
        // the next (all warps are inside iter 'it' => reading buf[it%3]).
        if (it + 2 < iters) stage(it + 2);
    }

    const int r0 = lane >> 2;
    const int cp = (lane & 3) * 2;
    #pragma unroll
    for (int mt = 0; mt < 4; mt++) {
        #pragma unroll
        for (int nt = 0; nt < 4; nt++) {
            const int gc = bn0 + wn * 32 + nt * 8 + cp;
            const float2 bv = *(const float2*)(bias + gc);
            #pragma unroll
            for (int h = 0; h < 2; h++) {
                const int gr = bm0 + wm * 64 + mt * 16 + r0 + h * 8;
                float ox = acc[mt][nt][2 * h + 0] + bv.x;
                float oy = acc[mt][nt][2 * h + 1] + bv.y;
                if (SPLIT) {
                    uint32_t hi, lo;
                    split2(ox, oy, hi, lo);
                    *(uint32_t*)(Chi + (size_t)gr * N + gc) = hi;
                    *(uint32_t*)(Clo + (size_t)gr * N + gc) = lo;
                } else {
                    if (RESID) {
                        float2 rv = *(const float2*)(res + (size_t)gr * N + gc);
                        ox += rv.x; oy += rv.y;
                    }
                    float2 o; o.x = ox; o.y = oy;
                    *(float2*)(C + (size_t)gr * N + gc) = o;
                }
            }
        }
    }
}

// ---------------------------------------------------------------------------
// Tensor-core causal flash attention, DOUBLE-BUFFERED K/V (1 sync/iter).
// Grid (S/128, H, B), 256 thr (8 warps), each warp owns 16 query rows.
// ---------------------------------------------------------------------------
#define QTILE 128
#define KTILE 64
#define SROW 72
#define KVBUF (4 * KTILE * SROW)         // 18,432 elems = 36,864 B / buffer
#define ASMEM_BYTES (2 * KVBUF * 2)      // 73,728 B

__global__ __launch_bounds__(256, 1) void attn_mma(
    const bf* __restrict__ qkv_hi, const bf* __restrict__ qkv_lo,
    bf* __restrict__ out_hi, bf* __restrict__ out_lo)
{
    extern __shared__ __align__(16) bf dsm[];

    const int tid  = threadIdx.x;
    const int lane = tid & 31;
    const int warp = tid >> 5;
    const int qt = blockIdx.x;
    const int h  = blockIdx.y;
    const int bz = blockIdx.z;

    const size_t rowstride = QKV_N;
    const size_t batch_row = (size_t)bz * SLEN;

    // ---- stage Q tile into buffer 0 region, grab fragments ----
    {
        bf* sQh = dsm;
        bf* sQl = dsm + QTILE * SROW;
        for (int i = tid; i < QTILE * 16; i += 256) {
            const int r = i >> 4;
            const int c = (i & 15) * 4;
            const size_t g = (batch_row + qt * QTILE + r) * rowstride + h * HDIM + c;
            *(uint2*)&sQh[r * SROW + c] = *(const uint2*)(qkv_hi + g);
            *(uint2*)&sQl[r * SROW + c] = *(const uint2*)(qkv_lo + g);
        }
    }
    __syncthreads();

    uint32_t qh[4][4], ql[4][4];
    {
        bf* sQh = dsm;
        bf* sQl = dsm + QTILE * SROW;
        const int arow = warp * 16 + (lane & 15);
        #pragma unroll
        for (int ks = 0; ks < 4; ks++) {
            const int acol = ks * 16 + (lane >> 4) * 8;
            ldsm4(cvta_smem(&sQh[arow * SROW + acol]),
                  qh[ks][0], qh[ks][1], qh[ks][2], qh[ks][3]);
            ldsm4(cvta_smem(&sQl[arow * SROW + acol]),
                  ql[ks][0], ql[ks][1], ql[ks][2], ql[ks][3]);
        }
    }
    __syncthreads();   // before K/V staging overwrites the Q region

    const int base = qt * QTILE + warp * 16;
    const int ktmax_warp = 2 * qt + (warp >= 4 ? 1 : 0);
    const int nkt = 2 * qt + 2;

    uint2 pkh[4], pkl[4], pvh[4], pvl[4];
    int pr[4], pc[4];
    #pragma unroll
    for (int j = 0; j < 4; j++) {
        const int i = tid + j * 256;
        pr[j] = i >> 4;
        pc[j] = (i & 15) * 4;
    }

    auto prefetch = [&](int kt) {
        #pragma unroll
        for (int j = 0; j < 4; j++) {
            const size_t gk = (batch_row + kt * KTILE + pr[j]) * rowstride
                              + DMODEL + h * HDIM + pc[j];
            pkh[j] = *(const uint2*)(qkv_hi + gk);
            pkl[j] = *(const uint2*)(qkv_lo + gk);
            pvh[j] = *(const uint2*)(qkv_hi + gk + DMODEL);
            pvl[j] = *(const uint2*)(qkv_lo + gk + DMODEL);
        }
    };
    auto stash = [&](bf* b) {
        bf* sKh = b;
        bf* sKl = b + KTILE * SROW;
        bf* sVh = b + 2 * KTILE * SROW;
        bf* sVl = b + 3 * KTILE * SROW;
        #pragma unroll
        for (int j = 0; j < 4; j++) {
            const int o = pr[j] * SROW + pc[j];
            *(uint2*)&sKh[o] = pkh[j];
            *(uint2*)&sKl[o] = pkl[j];
            *(uint2*)&sVh[o] = pvh[j];
            *(uint2*)&sVl[o] = pvl[j];
        }
    };

    float o[8][4];
    #pragma unroll
    for (int nt = 0; nt < 8; nt++)
        #pragma unroll
        for (int e = 0; e < 4; e++) o[nt][e] = 0.0f;
    float m_a = -1e30f, m_b = -1e30f, l_a = 0.0f, l_b = 0.0f;

    prefetch(0);
    stash(dsm);
    __syncthreads();

    for (int kt = 0; kt < nkt; kt++) {
        bf* buf = dsm + (kt & 1) * KVBUF;
        bf* sKh = buf;
        bf* sKl = buf + KTILE * SROW;
        bf* sVh = buf + 2 * KTILE * SROW;
        bf* sVl = buf + 3 * KTILE * SROW;

        if (kt + 1 < nkt) prefetch(kt + 1);

        if (kt <= ktmax_warp) {
            float s[8][4];
            #pragma unroll
            for (int nt = 0; nt < 8; nt++)
                #pragma unroll
                for (int e = 0; e < 4; e++) s[nt][e] = 0.0f;

            #pragma unroll
            for (int ks = 0; ks < 4; ks++) {
                #pragma unroll
                for (int np = 0; np < 4; np++) {
                    uint32_t kh0, kh1, kh2, kh3, kl0, kl1, kl2, kl3;
                    const int addr = (np * 16 + (lane & 15)) * SROW
                                     + ks * 16 + (lane >> 4) * 8;
                    ldsm4(cvta_smem(&sKh[addr]), kh0, kh1, kh2, kh3);
                    ldsm4(cvta_smem(&sKl[addr]), kl0, kl1, kl2, kl3);
                    uint32_t beh[2] = {kh0, kh2}, boh[2] = {kh1, kh3};
                    uint32_t bel[2] = {kl0, kl2}, bol[2] = {kl1, kl3};
                    mma_bf16(s[2*np],   qh[ks], beh);
                    mma_bf16(s[2*np],   qh[ks], bel);
                    mma_bf16(s[2*np],   ql[ks], beh);
                    mma_bf16(s[2*np+1], qh[ks], boh);
                    mma_bf16(s[2*np+1], qh[ks], bol);
                    mma_bf16(s[2*np+1], ql[ks], boh);
                }
            }

            if (kt * KTILE + 63 > base) {
                const int ra = base + (lane >> 2);
                #pragma unroll
                for (int nt = 0; nt < 8; nt++) {
                    const int kc = kt * KTILE + nt * 8 + (lane & 3) * 2;
                    if (kc > ra)      s[nt][0] = -1e30f;
                    if (kc + 1 > ra)  s[nt][1] = -1e30f;
                    if (kc > ra + 8)     s[nt][2] = -1e30f;
                    if (kc + 1 > ra + 8) s[nt][3] = -1e30f;
                }
            }

            float ta = -1e30f, tb = -1e30f;
            #pragma unroll
            for (int nt = 0; nt < 8; nt++) {
                ta = fmaxf(ta, fmaxf(s[nt][0], s[nt][1]));
                tb = fmaxf(tb, fmaxf(s[nt][2], s[nt][3]));
            }
            ta = fmaxf(ta, __shfl_xor_sync(0xffffffffu, ta, 1));
            ta = fmaxf(ta, __shfl_xor_sync(0xffffffffu, ta, 2));
            tb = fmaxf(tb, __shfl_xor_sync(0xffffffffu, tb, 1));
            tb = fmaxf(tb, __shfl_xor_sync(0xffffffffu, tb, 2));

            const float mna = fmaxf(m_a, ta);
            const float mnb = fmaxf(m_b, tb);
            const float ca = __expf((m_a - mna) * SM_SCALE);
            const float cb = __expf((m_b - mnb) * SM_SCALE);
            m_a = mna; m_b = mnb;
            l_a *= ca; l_b *= cb;
            #pragma unroll
            for (int nt = 0; nt < 8; nt++) {
                o[nt][0] *= ca; o[nt][1] *= ca;
                o[nt][2] *= cb; o[nt][3] *= cb;
            }

            float sa = 0.0f, sb = 0.0f;
            #pragma unroll
            for (int nt = 0; nt < 8; nt++) {
                float p0 = __expf((s[nt][0] - mna) * SM_SCALE);
                float p1 = __expf((s[nt][1] - mna) * SM_SCALE);
                float p2 = __expf((s[nt][2] - mnb) * SM_SCALE);
                float p3 = __expf((s[nt][3] - mnb) * SM_SCALE);
                s[nt][0] = p0; s[nt][1] = p1; s[nt][2] = p2; s[nt][3] = p3;
                sa += p0 + p1; sb += p2 + p3;
            }
            sa += __shfl_xor_sync(0xffffffffu, sa, 1);
            sa += __shfl_xor_sync(0xffffffffu, sa, 2);
            sb += __shfl_xor_sync(0xffffffffu, sb, 1);
            sb += __shfl_xor_sync(0xffffffffu, sb, 2);
            l_a += sa; l_b += sb;

            #pragma unroll
            for (int ks = 0; ks < 4; ks++) {
                uint32_t pah[4], pal[4];
                split2(s[2*ks][0],   s[2*ks][1],   pah[0], pal[0]);
                split2(s[2*ks][2],   s[2*ks][3],   pah[1], pal[1]);
                split2(s[2*ks+1][0], s[2*ks+1][1], pah[2], pal[2]);
                split2(s[2*ks+1][2], s[2*ks+1][3], pah[3], pal[3]);
                #pragma unroll
                for (int np = 0; np < 4; np++) {
                    uint32_t vh0, vh1, vh2, vh3, vl0, vl1, vl2, vl3;
                    const int addr = (ks * 16 + (lane & 15)) * SROW
                                     + np * 16 + (lane >> 4) * 8;
                    ldsm4t(cvta_smem(&sVh[addr]), vh0, vh1, vh2, vh3);
                    ldsm4t(cvta_smem(&sVl[addr]), vl0, vl1, vl2, vl3);
                    uint32_t veh[2] = {vh0, vh1}, voh[2] = {vh2, vh3};
                    uint32_t vel[2] = {vl0, vl1}, vol[2] = {vl2, vl3};
                    mma_bf16(o[2*np],   pah, veh);
                    mma_bf16(o[2*np],   pah, vel);
                    mma_bf16(o[2*np],   pal, veh);
                    mma_bf16(o[2*np+1], pah, voh);
                    mma_bf16(o[2*np+1], pah, vol);
                    mma_bf16(o[2*np+1], pal, voh);
                }
            }
        }

        if (kt + 1 < nkt) stash(dsm + ((kt + 1) & 1) * KVBUF);
        __syncthreads();
    }

    const float ia = 1.0f / l_a;
    const float ib = 1.0f / l_b;
    const int ra = base + (lane >> 2);
    const size_t rowa = (batch_row + ra) * (size_t)DMODEL + h * HDIM;
    const size_t rowb = rowa + 8 * DMODEL;
    #pragma unroll
    for (int nt = 0; nt < 8; nt++) {
        const int col = nt * 8 + (lane & 3) * 2;
        uint32_t hi, lo;
        split2(o[nt][0] * ia, o[nt][1] * ia, hi, lo);
        *(uint32_t*)(out_hi + rowa + col) = hi;
        *(uint32_t*)(out_lo + rowa + col) = lo;
        split2(o[nt][2] * ib, o[nt][3] * ib, hi, lo);
        *(uint32_t*)(out_hi + rowb + col) = hi;
        *(uint32_t*)(out_lo + rowb + col) = lo;
    }
}

// ---------------------------------------------------------------------------
// LayerNorm over last dim, in-place. One block (256 thr) per row of 1024.
// ---------------------------------------------------------------------------
__global__ __launch_bounds__(256) void ln_kernel(
    float* __restrict__ io, const float* __restrict__ gamma,
    const float* __restrict__ beta)
{
    const int row = blockIdx.x;
    const int tid = threadIdx.x;
    float4* p = (float4*)(io + (size_t)row * DMODEL);
    float4 v = p[tid];

    float s  = v.x + v.y + v.z + v.w;
    float s2 = fmaf(v.x, v.x, fmaf(v.y, v.y, fmaf(v.z, v.z, v.w * v.w)));

    #pragma unroll
    for (int ofs = 16; ofs; ofs >>= 1) {
        s  += __shfl_xor_sync(0xffffffffu, s, ofs);
        s2 += __shfl_xor_sync(0xffffffffu, s2, ofs);
    }
    __shared__ float shs[8], shs2[8];
    const int w = tid >> 5, l = tid & 31;
    if (l == 0) { shs[w] = s; shs2[w] = s2; }
    __syncthreads();
    if (tid < 32) {
        float a  = (l < 8) ? shs[l]  : 0.0f;
        float a2 = (l < 8) ? shs2[l] : 0.0f;
        #pragma unroll
        for (int ofs = 4; ofs; ofs >>= 1) {
            a  += __shfl_xor_sync(0xffffffffu, a, ofs);
            a2 += __shfl_xor_sync(0xffffffffu, a2, ofs);
        }
        if (l == 0) { shs[0] = a; shs2[0] = a2; }
    }
    __syncthreads();

    const float mean = shs[0] * (1.0f / DMODEL);
    const float var  = shs2[0] * (1.0f / DMODEL) - mean * mean;
    const float rstd = rsqrtf(var + LN_EPS);

    float4 g  = ((const float4*)gamma)[tid];
    float4 be = ((const float4*)beta)[tid];
    float4 r;
    r.x = (v.x - mean) * rstd * g.x + be.x;
    r.y = (v.y - mean) * rstd * g.y + be.y;
    r.z = (v.z - mean) * rstd * g.z + be.z;
    r.w = (v.w - mean) * rstd * g.w + be.w;
    p[tid] = r;
}

// ---------------------------------------------------------------------------
extern "C" void kernel_launch(void* const* d_in, const int* in_sizes, int n_in,
                              void* d_out, int out_size)
{
    const float* x     = (const float*)d_in[0];
    const float* Wqkv  = (const float*)d_in[1];
    const float* bqkv  = (const float*)d_in[2];
    const float* Wout  = (const float*)d_in[3];
    const float* bout  = (const float*)d_in[4];
    const float* gamma = (const float*)d_in[5];
    const float* beta  = (const float*)d_in[6];
    float* out = (float*)d_out;

    bf *xhi, *xlo, *wqh, *wql, *woh, *wol, *qh, *qlo, *ahi, *alo;
    cudaGetSymbolAddress((void**)&xhi, g_xhi);
    cudaGetSymbolAddress((void**)&xlo, g_xlo);
    cudaGetSymbolAddress((void**)&wqh, g_wqkv_hi);
    cudaGetSymbolAddress((void**)&wql, g_wqkv_lo);
    cudaGetSymbolAddress((void**)&woh, g_wout_hi);
    cudaGetSymbolAddress((void**)&wol, g_wout_lo);
    cudaGetSymbolAddress((void**)&qh,  g_qkv_hi);
    cudaGetSymbolAddress((void**)&qlo, g_qkv_lo);
    cudaGetSymbolAddress((void**)&ahi, g_attn_hi);
    cudaGetSymbolAddress((void**)&alo, g_attn_lo);

    static bool attrs_set = false;
    if (!attrs_set) {
        cudaFuncSetAttribute(mma_gemm<false, true>,
                             cudaFuncAttributeMaxDynamicSharedMemorySize, GSMEM_BYTES);
        cudaFuncSetAttribute(mma_gemm<true, false>,
                             cudaFuncAttributeMaxDynamicSharedMemorySize, GSMEM_BYTES);
        cudaFuncSetAttribute(attn_mma,
                             cudaFuncAttributeMaxDynamicSharedMemorySize, ASMEM_BYTES);
        attrs_set = true;
    }

    // 0) fp32 -> bf16 hi/lo splits of inputs
    {
        int n4 = MROWS * DMODEL / 4;
        cvt_kernel<<<(n4 + 255) / 256, 256>>>((const float4*)x, (uint2*)xhi, (uint2*)xlo, n4);
        n4 = DMODEL * QKV_N / 4;
        cvt_kernel<<<(n4 + 255) / 256, 256>>>((const float4*)Wqkv, (uint2*)wqh, (uint2*)wql, n4);
        n4 = DMODEL * DMODEL / 4;
        cvt_kernel<<<(n4 + 255) / 256, 256>>>((const float4*)Wout, (uint2*)woh, (uint2*)wol, n4);
    }
    // 1) QKV projection -> split bf16 output
    {
        dim3 grid(QKV_N / BN, MROWS / BM);
        mma_gemm<false, true><<<grid, 256, GSMEM_BYTES>>>(
            xhi, xlo, wqh, wql, bqkv, nullptr, nullptr, qh, qlo,
            MROWS, QKV_N, DMODEL);
    }
    // 2) tensor-core causal flash attention -> split bf16 output
    {
        dim3 grid(SLEN / QTILE, NHEADS, BATCH);
        attn_mma<<<grid, 256, ASMEM_BYTES>>>(qh, qlo, ahi, alo);
    }
    // 3) out projection + bias + residual -> fp32
    {
        dim3 grid(DMODEL / BN, MROWS / BM);
        mma_gemm<true, false><<<grid, 256, GSMEM_BYTES>>>(
            ahi, alo, woh, wol, bout, x, out, nullptr, nullptr,
            MROWS, DMODEL, DMODEL);
    }
    // 4) LayerNorm in-place on d_out
    ln_kernel<<<MROWS, 256>>>(out, gamma, beta);
}

// round 7
// speedup vs baseline: 1.3674x; 1.3674x over previous
#include <cuda_runtime.h>
#include <cuda_bf16.h>
#include <cstdint>

#define BATCH 8
#define SLEN 1024
#define DMODEL 1024
#define NHEADS 16
#define HDIM 64
#define MROWS (BATCH * SLEN)       // 8192
#define QKV_N (3 * DMODEL)         // 3072
#define LN_EPS 1e-5f
#define SM_SCALE 0.03125f          // 1/sqrt(1024)

typedef __nv_bfloat16 bf;

// Scratch (static device globals: allocation-free rule)
__device__ bf g_xhi[(size_t)MROWS * DMODEL];
__device__ bf g_xlo[(size_t)MROWS * DMODEL];
__device__ bf g_wqkv_hi[(size_t)DMODEL * QKV_N];
__device__ bf g_wqkv_lo[(size_t)DMODEL * QKV_N];
__device__ bf g_wout_hi[(size_t)DMODEL * DMODEL];
__device__ bf g_wout_lo[(size_t)DMODEL * DMODEL];
__device__ bf g_qkv_hi[(size_t)MROWS * QKV_N];
__device__ bf g_qkv_lo[(size_t)MROWS * QKV_N];
__device__ bf g_attn_hi[(size_t)MROWS * DMODEL];
__device__ bf g_attn_lo[(size_t)MROWS * DMODEL];

// ---------------------------------------------------------------------------
// helpers
// ---------------------------------------------------------------------------
__device__ __forceinline__ uint32_t cvta_smem(const void* p) {
    uint32_t a;
    asm("{.reg .u64 t; cvta.to.shared.u64 t, %1; cvt.u32.u64 %0, t;}"
        : "=r"(a) : "l"(p));
    return a;
}
__device__ __forceinline__ void ldsm4(uint32_t a, uint32_t& r0, uint32_t& r1,
                                      uint32_t& r2, uint32_t& r3) {
    asm volatile("ldmatrix.sync.aligned.m8n8.x4.shared.b16 {%0,%1,%2,%3},[%4];"
                 : "=r"(r0), "=r"(r1), "=r"(r2), "=r"(r3) : "r"(a));
}
__device__ __forceinline__ void ldsm4t(uint32_t a, uint32_t& r0, uint32_t& r1,
                                       uint32_t& r2, uint32_t& r3) {
    asm volatile("ldmatrix.sync.aligned.m8n8.x4.trans.shared.b16 {%0,%1,%2,%3},[%4];"
                 : "=r"(r0), "=r"(r1), "=r"(r2), "=r"(r3) : "r"(a));
}
__device__ __forceinline__ void mma_bf16(float* c, const uint32_t* a,
                                         const uint32_t* b) {
    asm volatile(
        "mma.sync.aligned.m16n8k16.row.col.f32.bf16.bf16.f32 "
        "{%0,%1,%2,%3},{%4,%5,%6,%7},{%8,%9},{%0,%1,%2,%3};"
        : "+f"(c[0]), "+f"(c[1]), "+f"(c[2]), "+f"(c[3])
        : "r"(a[0]), "r"(a[1]), "r"(a[2]), "r"(a[3]), "r"(b[0]), "r"(b[1]));
}
__device__ __forceinline__ void split2(float x, float y, uint32_t& hi,
                                       uint32_t& lo) {
    bf hx = __float2bfloat16(x), hy = __float2bfloat16(y);
    bf lx = __float2bfloat16(x - __bfloat162float(hx));
    bf ly = __float2bfloat16(y - __bfloat162float(hy));
    __nv_bfloat162 h = __halves2bfloat162(hx, hy);
    __nv_bfloat162 l = __halves2bfloat162(lx, ly);
    hi = *(uint32_t*)&h;
    lo = *(uint32_t*)&l;
}

// ---------------------------------------------------------------------------
// fp32 -> (bf16 hi, bf16 lo) split conversion, vectorized by 4
// ---------------------------------------------------------------------------
__global__ __launch_bounds__(256) void cvt_kernel(
    const float4* __restrict__ in, uint2* __restrict__ hi,
    uint2* __restrict__ lo, int n4)
{
    int i = blockIdx.x * blockDim.x + threadIdx.x;
    if (i >= n4) return;
    float4 v = in[i];
    uint2 ho, loo;
    split2(v.x, v.y, ho.x, loo.x);
    split2(v.z, v.w, ho.y, loo.y);
    hi[i] = ho;
    lo[i] = loo;
}

// ---------------------------------------------------------------------------
// Tensor-core GEMM, bf16x2-split inputs, 3-buffer rotation.
// STS for buffer it+2 issued at the TOP of iter it (retires during compute),
// so the end-of-iter barrier sees ~0 STS in flight (no BAR drain penalty).
// BM=BN=128, BK=32, 8 warps (64x32 warp tiles).
// ---------------------------------------------------------------------------
#define BM 128
#define BN 128
#define BK 32
#define A_STR 40        // BK + 8 pad
#define B_STR 136       // BN + 8 pad
#define ABUF (BM * A_STR)                 // 5120 elems per hi/lo
#define BBUF (BK * B_STR)                 // 4352 elems per hi/lo
#define GBUF_ELEMS (2 * ABUF + 2 * BBUF)  // 18944 elems = 37,888 B / buffer
#define GNSTAGE 3
#define GSMEM_BYTES (GNSTAGE * GBUF_ELEMS * 2)  // 113,664 B

template <bool RESID, bool SPLIT>
__global__ __launch_bounds__(256, 1) void mma_gemm(
    const bf* __restrict__ Ahi, const bf* __restrict__ Alo,
    const bf* __restrict__ Bhi, const bf* __restrict__ Blo,
    const float* __restrict__ bias, const float* __restrict__ res,
    float* __restrict__ C, bf* __restrict__ Chi, bf* __restrict__ Clo,
    int M, int N, int K)
{
    extern __shared__ __align__(16) bf dsm[];

    const int tid = threadIdx.x;
    const int lane = tid & 31;
    const int warp = tid >> 5;
    const int wm = warp >> 2;
    const int wn = warp & 3;
    const int bm0 = blockIdx.y * BM;
    const int bn0 = blockIdx.x * BN;

    const int ar = tid >> 2;          // 0..63 (rows ar, ar+64)
    const int ac = (tid & 3) * 8;     // k offset
    const int br = tid >> 3;          // 0..31
    const int bc = (tid & 7) * 16;    // n offset

    float acc[4][4][4];
    #pragma unroll
    for (int i = 0; i < 4; i++)
        #pragma unroll
        for (int j = 0; j < 4; j++)
            #pragma unroll
            for (int c = 0; c < 4; c++) acc[i][j][c] = 0.0f;

    const bf* Ah = Ahi + (size_t)(bm0 + ar) * K + ac;
    const bf* Al = Alo + (size_t)(bm0 + ar) * K + ac;
    const bf* Bh = Bhi + (size_t)br * N + bn0 + bc;
    const bf* Bl = Blo + (size_t)br * N + bn0 + bc;

    uint4 pa[4], pb[4];
    auto ldgs = [&](int it) {
        const size_t ka = (size_t)it * BK;
        pa[0] = *(const uint4*)(Ah + ka);
        pa[1] = *(const uint4*)(Ah + (size_t)64 * K + ka);
        pa[2] = *(const uint4*)(Al + ka);
        pa[3] = *(const uint4*)(Al + (size_t)64 * K + ka);
        const size_t kb = ka * N;
        pb[0] = *(const uint4*)(Bh + kb);
        pb[1] = *(const uint4*)(Bh + kb + 8);
        pb[2] = *(const uint4*)(Bl + kb);
        pb[3] = *(const uint4*)(Bl + kb + 8);
    };
    auto stash = [&](int it) {
        bf* buf = dsm + (it % GNSTAGE) * GBUF_ELEMS;
        bf* sAh = buf;
        bf* sAl = buf + ABUF;
        bf* sBh = buf + 2 * ABUF;
        bf* sBl = buf + 2 * ABUF + BBUF;
        uint2* d; const uint2* s;
        d = (uint2*)&sAh[ar * A_STR + ac];        s = (const uint2*)&pa[0]; d[0]=s[0]; d[1]=s[1];
        d = (uint2*)&sAh[(ar + 64) * A_STR + ac]; s = (const uint2*)&pa[1]; d[0]=s[0]; d[1]=s[1];
        d = (uint2*)&sAl[ar * A_STR + ac];        s = (const uint2*)&pa[2]; d[0]=s[0]; d[1]=s[1];
        d = (uint2*)&sAl[(ar + 64) * A_STR + ac]; s = (const uint2*)&pa[3]; d[0]=s[0]; d[1]=s[1];
        d = (uint2*)&sBh[br * B_STR + bc];        s = (const uint2*)&pb[0]; d[0]=s[0]; d[1]=s[1];
        d = (uint2*)&sBh[br * B_STR + bc + 8];    s = (const uint2*)&pb[1]; d[0]=s[0]; d[1]=s[1];
        d = (uint2*)&sBl[br * B_STR + bc];        s = (const uint2*)&pb[2]; d[0]=s[0]; d[1]=s[1];
        d = (uint2*)&sBl[br * B_STR + bc + 8];    s = (const uint2*)&pb[3]; d[0]=s[0]; d[1]=s[1];
    };

    const int iters = K / BK;

    // prologue: buffers 0 and 1 staged; LDGs for chunk 2 in registers
    ldgs(0); stash(0);
    ldgs(1); stash(1);
    if (iters > 2) ldgs(2);
    __syncthreads();

    for (int it = 0; it < iters; it++) {
        // STS for buffer it+2 (data already in regs); retires during compute.
        if (it + 2 < iters) stash(it + 2);
        if (it + 3 < iters) ldgs(it + 3);

        bf* buf = dsm + (it % GNSTAGE) * GBUF_ELEMS;
        bf* sAh = buf;
        bf* sAl = buf + ABUF;
        bf* sBh = buf + 2 * ABUF;
        bf* sBl = buf + 2 * ABUF + BBUF;

        #pragma unroll
        for (int kk = 0; kk < 2; kk++) {
            uint32_t ah[4][4], al[4][4], bh[4][2], bl[4][2];
            const int arow = wm * 64 + (lane & 15);
            const int acol = kk * 16 + (lane >> 4) * 8;
            #pragma unroll
            for (int mt = 0; mt < 4; mt++) {
                ldsm4(cvta_smem(&sAh[(arow + mt * 16) * A_STR + acol]),
                      ah[mt][0], ah[mt][1], ah[mt][2], ah[mt][3]);
                ldsm4(cvta_smem(&sAl[(arow + mt * 16) * A_STR + acol]),
                      al[mt][0], al[mt][1], al[mt][2], al[mt][3]);
            }
            const int brow = kk * 16 + (lane & 15);
            #pragma unroll
            for (int ng = 0; ng < 2; ng++) {
                const int bcol = wn * 32 + ng * 16 + (lane >> 4) * 8;
                ldsm4t(cvta_smem(&sBh[brow * B_STR + bcol]),
                       bh[2*ng][0], bh[2*ng][1], bh[2*ng+1][0], bh[2*ng+1][1]);
                ldsm4t(cvta_smem(&sBl[brow * B_STR + bcol]),
                       bl[2*ng][0], bl[2*ng][1], bl[2*ng+1][0], bl[2*ng+1][1]);
            }
            #pragma unroll
            for (int mt = 0; mt < 4; mt++)
                #pragma unroll
                for (int nt = 0; nt < 4; nt++) {
                    mma_bf16(acc[mt][nt], ah[mt], bh[nt]);
                    mma_bf16(acc[mt][nt], ah[mt], bl[nt]);
                    mma_bf16(acc[mt][nt], al[mt], bh[nt]);
                }
        }
        __syncthreads();
    }

    const int r0 = lane >> 2;
    const int cp = (lane & 3) * 2;
    #pragma unroll
    for (int mt = 0; mt < 4; mt++) {
        #pragma unroll
        for (int nt = 0; nt < 4; nt++) {
            const int gc = bn0 + wn * 32 + nt * 8 + cp;
            const float2 bv = *(const float2*)(bias + gc);
            #pragma unroll
            for (int h = 0; h < 2; h++) {
                const int gr = bm0 + wm * 64 + mt * 16 + r0 + h * 8;
                float ox = acc[mt][nt][2 * h + 0] + bv.x;
                float oy = acc[mt][nt][2 * h + 1] + bv.y;
                if (SPLIT) {
                    uint32_t hi, lo;
                    split2(ox, oy, hi, lo);
                    *(uint32_t*)(Chi + (size_t)gr * N + gc) = hi;
                    *(uint32_t*)(Clo + (size_t)gr * N + gc) = lo;
                } else {
                    if (RESID) {
                        float2 rv = *(const float2*)(res + (size_t)gr * N + gc);
                        ox += rv.x; oy += rv.y;
                    }
                    float2 o; o.x = ox; o.y = oy;
                    *(float2*)(C + (size_t)gr * N + gc) = o;
                }
            }
        }
    }
}

// ---------------------------------------------------------------------------
// Tensor-core causal flash attention, 3-buffer K/V rotation (stash-at-top).
// Grid (S/128, H, B), 256 thr (8 warps), each warp owns 16 query rows.
// ---------------------------------------------------------------------------
#define QTILE 128
#define KTILE 64
#define SROW 72
#define KVBUF (4 * KTILE * SROW)          // 18,432 elems = 36,864 B / buffer
#define ANSTAGE 3
#define ASMEM_BYTES (ANSTAGE * KVBUF * 2) // 110,592 B

__global__ __launch_bounds__(256, 1) void attn_mma(
    const bf* __restrict__ qkv_hi, const bf* __restrict__ qkv_lo,
    bf* __restrict__ out_hi, bf* __restrict__ out_lo)
{
    extern __shared__ __align__(16) bf dsm[];

    const int tid  = threadIdx.x;
    const int lane = tid & 31;
    const int warp = tid >> 5;
    const int qt = blockIdx.x;
    const int h  = blockIdx.y;
    const int bz = blockIdx.z;

    const size_t rowstride = QKV_N;
    const size_t batch_row = (size_t)bz * SLEN;

    // ---- stage Q tile into buffer 0 region, grab fragments ----
    {
        bf* sQh = dsm;
        bf* sQl = dsm + QTILE * SROW;
        for (int i = tid; i < QTILE * 16; i += 256) {
            const int r = i >> 4;
            const int c = (i & 15) * 4;
            const size_t g = (batch_row + qt * QTILE + r) * rowstride + h * HDIM + c;
            *(uint2*)&sQh[r * SROW + c] = *(const uint2*)(qkv_hi + g);
            *(uint2*)&sQl[r * SROW + c] = *(const uint2*)(qkv_lo + g);
        }
    }
    __syncthreads();

    uint32_t qh[4][4], ql[4][4];
    {
        bf* sQh = dsm;
        bf* sQl = dsm + QTILE * SROW;
        const int arow = warp * 16 + (lane & 15);
        #pragma unroll
        for (int ks = 0; ks < 4; ks++) {
            const int acol = ks * 16 + (lane >> 4) * 8;
            ldsm4(cvta_smem(&sQh[arow * SROW + acol]),
                  qh[ks][0], qh[ks][1], qh[ks][2], qh[ks][3]);
            ldsm4(cvta_smem(&sQl[arow * SROW + acol]),
                  ql[ks][0], ql[ks][1], ql[ks][2], ql[ks][3]);
        }
    }
    __syncthreads();   // before K/V staging overwrites the Q region

    const int base = qt * QTILE + warp * 16;
    const int ktmax_warp = 2 * qt + (warp >= 4 ? 1 : 0);
    const int nkt = 2 * qt + 2;

    uint2 pkh[4], pkl[4], pvh[4], pvl[4];
    int pr[4], pc[4];
    #pragma unroll
    for (int j = 0; j < 4; j++) {
        const int i = tid + j * 256;
        pr[j] = i >> 4;
        pc[j] = (i & 15) * 4;
    }

    auto prefetch = [&](int kt) {
        #pragma unroll
        for (int j = 0; j < 4; j++) {
            const size_t gk = (batch_row + kt * KTILE + pr[j]) * rowstride
                              + DMODEL + h * HDIM + pc[j];
            pkh[j] = *(const uint2*)(qkv_hi + gk);
            pkl[j] = *(const uint2*)(qkv_lo + gk);
            pvh[j] = *(const uint2*)(qkv_hi + gk + DMODEL);
            pvl[j] = *(const uint2*)(qkv_lo + gk + DMODEL);
        }
    };
    auto stash = [&](int kt) {
        bf* b = dsm + (kt % ANSTAGE) * KVBUF;
        bf* sKh = b;
        bf* sKl = b + KTILE * SROW;
        bf* sVh = b + 2 * KTILE * SROW;
        bf* sVl = b + 3 * KTILE * SROW;
        #pragma unroll
        for (int j = 0; j < 4; j++) {
            const int o = pr[j] * SROW + pc[j];
            *(uint2*)&sKh[o] = pkh[j];
            *(uint2*)&sKl[o] = pkl[j];
            *(uint2*)&sVh[o] = pvh[j];
            *(uint2*)&sVl[o] = pvl[j];
        }
    };

    float o[8][4];
    #pragma unroll
    for (int nt = 0; nt < 8; nt++)
        #pragma unroll
        for (int e = 0; e < 4; e++) o[nt][e] = 0.0f;
    float m_a = -1e30f, m_b = -1e30f, l_a = 0.0f, l_b = 0.0f;

    // prologue: buffer 0 staged; LDGs for tile 1 in registers
    prefetch(0);
    stash(0);
    if (nkt > 1) prefetch(1);
    __syncthreads();

    for (int kt = 0; kt < nkt; kt++) {
        // stash tile kt+1 (regs already loaded); retires during compute
        if (kt + 1 < nkt) stash(kt + 1);
        if (kt + 2 < nkt) prefetch(kt + 2);

        bf* buf = dsm + (kt % ANSTAGE) * KVBUF;
        bf* sKh = buf;
        bf* sKl = buf + KTILE * SROW;
        bf* sVh = buf + 2 * KTILE * SROW;
        bf* sVl = buf + 3 * KTILE * SROW;

        if (kt <= ktmax_warp) {
            float s[8][4];
            #pragma unroll
            for (int nt = 0; nt < 8; nt++)
                #pragma unroll
                for (int e = 0; e < 4; e++) s[nt][e] = 0.0f;

            #pragma unroll
            for (int ks = 0; ks < 4; ks++) {
                #pragma unroll
                for (int np = 0; np < 4; np++) {
                    uint32_t kh0, kh1, kh2, kh3, kl0, kl1, kl2, kl3;
                    const int addr = (np * 16 + (lane & 15)) * SROW
                                     + ks * 16 + (lane >> 4) * 8;
                    ldsm4(cvta_smem(&sKh[addr]), kh0, kh1, kh2, kh3);
                    ldsm4(cvta_smem(&sKl[addr]), kl0, kl1, kl2, kl3);
                    uint32_t beh[2] = {kh0, kh2}, boh[2] = {kh1, kh3};
                    uint32_t bel[2] = {kl0, kl2}, bol[2] = {kl1, kl3};
                    mma_bf16(s[2*np],   qh[ks], beh);
                    mma_bf16(s[2*np],   qh[ks], bel);
                    mma_bf16(s[2*np],   ql[ks], beh);
                    mma_bf16(s[2*np+1], qh[ks], boh);
                    mma_bf16(s[2*np+1], qh[ks], bol);
                    mma_bf16(s[2*np+1], ql[ks], boh);
                }
            }

            if (kt * KTILE + 63 > base) {
                const int ra = base + (lane >> 2);
                #pragma unroll
                for (int nt = 0; nt < 8; nt++) {
                    const int kc = kt * KTILE + nt * 8 + (lane & 3) * 2;
                    if (kc > ra)      s[nt][0] = -1e30f;
                    if (kc + 1 > ra)  s[nt][1] = -1e30f;
                    if (kc > ra + 8)     s[nt][2] = -1e30f;
                    if (kc + 1 > ra + 8) s[nt][3] = -1e30f;
                }
            }

            float ta = -1e30f, tb = -1e30f;
            #pragma unroll
            for (int nt = 0; nt < 8; nt++) {
                ta = fmaxf(ta, fmaxf(s[nt][0], s[nt][1]));
                tb = fmaxf(tb, fmaxf(s[nt][2], s[nt][3]));
            }
            ta = fmaxf(ta, __shfl_xor_sync(0xffffffffu, ta, 1));
            ta = fmaxf(ta, __shfl_xor_sync(0xffffffffu, ta, 2));
            tb = fmaxf(tb, __shfl_xor_sync(0xffffffffu, tb, 1));
            tb = fmaxf(tb, __shfl_xor_sync(0xffffffffu, tb, 2));

            const float mna = fmaxf(m_a, ta);
            const float mnb = fmaxf(m_b, tb);
            const float ca = __expf((m_a - mna) * SM_SCALE);
            const float cb = __expf((m_b - mnb) * SM_SCALE);
            m_a = mna; m_b = mnb;
            l_a *= ca; l_b *= cb;
            #pragma unroll
            for (int nt = 0; nt < 8; nt++) {
                o[nt][0] *= ca; o[nt][1] *= ca;
                o[nt][2] *= cb; o[nt][3] *= cb;
            }

            float sa = 0.0f, sb = 0.0f;
            #pragma unroll
            for (int nt = 0; nt < 8; nt++) {
                float p0 = __expf((s[nt][0] - mna) * SM_SCALE);
                float p1 = __expf((s[nt][1] - mna) * SM_SCALE);
                float p2 = __expf((s[nt][2] - mnb) * SM_SCALE);
                float p3 = __expf((s[nt][3] - mnb) * SM_SCALE);
                s[nt][0] = p0; s[nt][1] = p1; s[nt][2] = p2; s[nt][3] = p3;
                sa += p0 + p1; sb += p2 + p3;
            }
            sa += __shfl_xor_sync(0xffffffffu, sa, 1);
            sa += __shfl_xor_sync(0xffffffffu, sa, 2);
            sb += __shfl_xor_sync(0xffffffffu, sb, 1);
            sb += __shfl_xor_sync(0xffffffffu, sb, 2);
            l_a += sa; l_b += sb;

            #pragma unroll
            for (int ks = 0; ks < 4; ks++) {
                uint32_t pah[4], pal[4];
                split2(s[2*ks][0],   s[2*ks][1],   pah[0], pal[0]);
                split2(s[2*ks][2],   s[2*ks][3],   pah[1], pal[1]);
                split2(s[2*ks+1][0], s[2*ks+1][1], pah[2], pal[2]);
                split2(s[2*ks+1][2], s[2*ks+1][3], pah[3], pal[3]);
                #pragma unroll
                for (int np = 0; np < 4; np++) {
                    uint32_t vh0, vh1, vh2, vh3, vl0, vl1, vl2, vl3;
                    const int addr = (ks * 16 + (lane & 15)) * SROW
                                     + np * 16 + (lane >> 4) * 8;
                    ldsm4t(cvta_smem(&sVh[addr]), vh0, vh1, vh2, vh3);
                    ldsm4t(cvta_smem(&sVl[addr]), vl0, vl1, vl2, vl3);
                    uint32_t veh[2] = {vh0, vh1}, voh[2] = {vh2, vh3};
                    uint32_t vel[2] = {vl0, vl1}, vol[2] = {vl2, vl3};
                    mma_bf16(o[2*np],   pah, veh);
                    mma_bf16(o[2*np],   pah, vel);
                    mma_bf16(o[2*np],   pal, veh);
                    mma_bf16(o[2*np+1], pah, voh);
                    mma_bf16(o[2*np+1], pah, vol);
                    mma_bf16(o[2*np+1], pal, voh);
                }
            }
        }

        __syncthreads();
    }

    const float ia = 1.0f / l_a;
    const float ib = 1.0f / l_b;
    const int ra = base + (lane >> 2);
    const size_t rowa = (batch_row + ra) * (size_t)DMODEL + h * HDIM;
    const size_t rowb = rowa + 8 * DMODEL;
    #pragma unroll
    for (int nt = 0; nt < 8; nt++) {
        const int col = nt * 8 + (lane & 3) * 2;
        uint32_t hi, lo;
        split2(o[nt][0] * ia, o[nt][1] * ia, hi, lo);
        *(uint32_t*)(out_hi + rowa + col) = hi;
        *(uint32_t*)(out_lo + rowa + col) = lo;
        split2(o[nt][2] * ib, o[nt][3] * ib, hi, lo);
        *(uint32_t*)(out_hi + rowb + col) = hi;
        *(uint32_t*)(out_lo + rowb + col) = lo;
    }
}

// ---------------------------------------------------------------------------
// LayerNorm over last dim, in-place. One block (256 thr) per row of 1024.
// ---------------------------------------------------------------------------
__global__ __launch_bounds__(256) void ln_kernel(
    float* __restrict__ io, const float* __restrict__ gamma,
    const float* __restrict__ beta)
{
    const int row = blockIdx.x;
    const int tid = threadIdx.x;
    float4* p = (float4*)(io + (size_t)row * DMODEL);
    float4 v = p[tid];

    float s  = v.x + v.y + v.z + v.w;
    float s2 = fmaf(v.x, v.x, fmaf(v.y, v.y, fmaf(v.z, v.z, v.w * v.w)));

    #pragma unroll
    for (int ofs = 16; ofs; ofs >>= 1) {
        s  += __shfl_xor_sync(0xffffffffu, s, ofs);
        s2 += __shfl_xor_sync(0xffffffffu, s2, ofs);
    }
    __shared__ float shs[8], shs2[8];
    const int w = tid >> 5, l = tid & 31;
    if (l == 0) { shs[w] = s; shs2[w] = s2; }
    __syncthreads();
    if (tid < 32) {
        float a  = (l < 8) ? shs[l]  : 0.0f;
        float a2 = (l < 8) ? shs2[l] : 0.0f;
        #pragma unroll
        for (int ofs = 4; ofs; ofs >>= 1) {
            a  += __shfl_xor_sync(0xffffffffu, a, ofs);
            a2 += __shfl_xor_sync(0xffffffffu, a2, ofs);
        }
        if (l == 0) { shs[0] = a; shs2[0] = a2; }
    }
    __syncthreads();

    const float mean = shs[0] * (1.0f / DMODEL);
    const float var  = shs2[0] * (1.0f / DMODEL) - mean * mean;
    const float rstd = rsqrtf(var + LN_EPS);

    float4 g  = ((const float4*)gamma)[tid];
    float4 be = ((const float4*)beta)[tid];
    float4 r;
    r.x = (v.x - mean) * rstd * g.x + be.x;
    r.y = (v.y - mean) * rstd * g.y + be.y;
    r.z = (v.z - mean) * rstd * g.z + be.z;
    r.w = (v.w - mean) * rstd * g.w + be.w;
    p[tid] = r;
}

// ---------------------------------------------------------------------------
extern "C" void kernel_launch(void* const* d_in, const int* in_sizes, int n_in,
                              void* d_out, int out_size)
{
    const float* x     = (const float*)d_in[0];
    const float* Wqkv  = (const float*)d_in[1];
    const float* bqkv  = (const float*)d_in[2];
    const float* Wout  = (const float*)d_in[3];
    const float* bout  = (const float*)d_in[4];
    const float* gamma = (const float*)d_in[5];
    const float* beta  = (const float*)d_in[6];
    float* out = (float*)d_out;

    bf *xhi, *xlo, *wqh, *wql, *woh, *wol, *qh, *qlo, *ahi, *alo;
    cudaGetSymbolAddress((void**)&xhi, g_xhi);
    cudaGetSymbolAddress((void**)&xlo, g_xlo);
    cudaGetSymbolAddress((void**)&wqh, g_wqkv_hi);
    cudaGetSymbolAddress((void**)&wql, g_wqkv_lo);
    cudaGetSymbolAddress((void**)&woh, g_wout_hi);
    cudaGetSymbolAddress((void**)&wol, g_wout_lo);
    cudaGetSymbolAddress((void**)&qh,  g_qkv_hi);
    cudaGetSymbolAddress((void**)&qlo, g_qkv_lo);
    cudaGetSymbolAddress((void**)&ahi, g_attn_hi);
    cudaGetSymbolAddress((void**)&alo, g_attn_lo);

    static bool attrs_set = false;
    if (!attrs_set) {
        cudaFuncSetAttribute(mma_gemm<false, true>,
                             cudaFuncAttributeMaxDynamicSharedMemorySize, GSMEM_BYTES);
        cudaFuncSetAttribute(mma_gemm<true, false>,
                             cudaFuncAttributeMaxDynamicSharedMemorySize, GSMEM_BYTES);
        cudaFuncSetAttribute(attn_mma,
                             cudaFuncAttributeMaxDynamicSharedMemorySize, ASMEM_BYTES);
        attrs_set = true;
    }

    // 0) fp32 -> bf16 hi/lo splits of inputs
    {
        int n4 = MROWS * DMODEL / 4;
        cvt_kernel<<<(n4 + 255) / 256, 256>>>((const float4*)x, (uint2*)xhi, (uint2*)xlo, n4);
        n4 = DMODEL * QKV_N / 4;
        cvt_kernel<<<(n4 + 255) / 256, 256>>>((const float4*)Wqkv, (uint2*)wqh, (uint2*)wql, n4);
        n4 = DMODEL * DMODEL / 4;
        cvt_kernel<<<(n4 + 255) / 256, 256>>>((const float4*)Wout, (uint2*)woh, (uint2*)wol, n4);
    }
    // 1) QKV projection -> split bf16 output
    {
        dim3 grid(QKV_N / BN, MROWS / BM);
        mma_gemm<false, true><<<grid, 256, GSMEM_BYTES>>>(
            xhi, xlo, wqh, wql, bqkv, nullptr, nullptr, qh, qlo,
            MROWS, QKV_N, DMODEL);
    }
    // 2) tensor-core causal flash attention -> split bf16 output
    {
        dim3 grid(SLEN / QTILE, NHEADS, BATCH);
        attn_mma<<<grid, 256, ASMEM_BYTES>>>(qh, qlo, ahi, alo);
    }
    // 3) out projection + bias + residual -> fp32
    {
        dim3 grid(DMODEL / BN, MROWS / BM);
        mma_gemm<true, false><<<grid, 256, GSMEM_BYTES>>>(
            ahi, alo, woh, wol, bout, x, out, nullptr, nullptr,
            MROWS, DMODEL, DMODEL);
    }
    // 4) LayerNorm in-place on d_out
    ln_kernel<<<MROWS, 256>>>(out, gamma, beta);
}

// round 9
// speedup vs baseline: 3.4096x; 2.4935x over previous
#include <cuda_runtime.h>
#include <cuda_fp16.h>
#include <cstdint>

#define BATCH 8
#define SLEN 1024
#define DMODEL 1024
#define NHEADS 16
#define HDIM 64
#define MROWS (BATCH * SLEN)       // 8192
#define QKV_N (3 * DMODEL)         // 3072
#define LN_EPS 1e-5f
#define SM_SCALE 0.03125f          // 1/sqrt(1024)

// Scratch (static device globals: allocation-free rule)
__device__ __half g_xh[(size_t)MROWS * DMODEL];
__device__ __half g_wqkv[(size_t)DMODEL * QKV_N];
__device__ __half g_wout[(size_t)DMODEL * DMODEL];
__device__ __half g_qkv[(size_t)MROWS * QKV_N];
__device__ __half g_attn[(size_t)MROWS * DMODEL];

// ---------------------------------------------------------------------------
// helpers
// ---------------------------------------------------------------------------
__device__ __forceinline__ uint32_t cvta_smem(const void* p) {
    uint32_t a;
    asm("{.reg .u64 t; cvta.to.shared.u64 t, %1; cvt.u32.u64 %0, t;}"
        : "=r"(a) : "l"(p));
    return a;
}
__device__ __forceinline__ void ldsm4(uint32_t a, uint32_t& r0, uint32_t& r1,
                                      uint32_t& r2, uint32_t& r3) {
    asm volatile("ldmatrix.sync.aligned.m8n8.x4.shared.b16 {%0,%1,%2,%3},[%4];"
                 : "=r"(r0), "=r"(r1), "=r"(r2), "=r"(r3) : "r"(a));
}
__device__ __forceinline__ void ldsm4t(uint32_t a, uint32_t& r0, uint32_t& r1,
                                       uint32_t& r2, uint32_t& r3) {
    asm volatile("ldmatrix.sync.aligned.m8n8.x4.trans.shared.b16 {%0,%1,%2,%3},[%4];"
                 : "=r"(r0), "=r"(r1), "=r"(r2), "=r"(r3) : "r"(a));
}
__device__ __forceinline__ void mma_fp16(float* c, const uint32_t* a,
                                         const uint32_t* b) {
    asm volatile(
        "mma.sync.aligned.m16n8k16.row.col.f32.f16.f16.f32 "
        "{%0,%1,%2,%3},{%4,%5,%6,%7},{%8,%9},{%0,%1,%2,%3};"
        : "+f"(c[0]), "+f"(c[1]), "+f"(c[2]), "+f"(c[3])
        : "r"(a[0]), "r"(a[1]), "r"(a[2]), "r"(a[3]), "r"(b[0]), "r"(b[1]));
}
__device__ __forceinline__ uint32_t pack_h2(float x, float y) {
    __half2 h = __floats2half2_rn(x, y);
    return *(uint32_t*)&h;
}

// ---------------------------------------------------------------------------
// fp32 -> fp16 conversion, vectorized by 4
// ---------------------------------------------------------------------------
__global__ __launch_bounds__(256) void cvt_kernel(
    const float4* __restrict__ in, uint2* __restrict__ outh, int n4)
{
    int i = blockIdx.x * blockDim.x + threadIdx.x;
    if (i >= n4) return;
    float4 v = in[i];
    uint2 o;
    o.x = pack_h2(v.x, v.y);
    o.y = pack_h2(v.z, v.w);
    outh[i] = o;
}

// ---------------------------------------------------------------------------
// Tensor-core GEMM, fp16 single-MMA, double-buffered smem (1 sync/iter).
// BM=BN=128, BK=32, 8 warps (64x32 warp tiles).
// ---------------------------------------------------------------------------
#define BM 128
#define BN 128
#define BK 32
#define A_STR 40        // BK + 8 pad
#define B_STR 136       // BN + 8 pad
#define ABUF (BM * A_STR)                 // 5120 elems
#define BBUF (BK * B_STR)                 // 4352 elems
#define GBUF_ELEMS (ABUF + BBUF)          // 9472 elems = 18,944 B / buffer
#define GSMEM_BYTES (2 * GBUF_ELEMS * 2)  // 37,888 B

template <bool RESID, bool HALF_OUT>
__global__ __launch_bounds__(256) void mma_gemm(
    const __half* __restrict__ Ah, const __half* __restrict__ Bh,
    const float* __restrict__ bias, const float* __restrict__ res,
    float* __restrict__ C, __half* __restrict__ Ch,
    int M, int N, int K)
{
    extern __shared__ __align__(16) __half dsm[];

    const int tid = threadIdx.x;
    const int lane = tid & 31;
    const int warp = tid >> 5;
    const int wm = warp >> 2;
    const int wn = warp & 3;
    const int bm0 = blockIdx.y * BM;
    const int bn0 = blockIdx.x * BN;

    const int ar = tid >> 2;          // 0..63 (rows ar, ar+64)
    const int ac = (tid & 3) * 8;     // k offset
    const int br = tid >> 3;          // 0..31
    const int bc = (tid & 7) * 16;    // n offset

    float acc[4][4][4];
    #pragma unroll
    for (int i = 0; i < 4; i++)
        #pragma unroll
        for (int j = 0; j < 4; j++)
            #pragma unroll
            for (int c = 0; c < 4; c++) acc[i][j][c] = 0.0f;

    const __half* Ap = Ah + (size_t)(bm0 + ar) * K + ac;
    const __half* Bp = Bh + (size_t)br * N + bn0 + bc;

    uint4 pa[2], pb[2];
    pa[0] = *(const uint4*)(Ap);
    pa[1] = *(const uint4*)(Ap + (size_t)64 * K);
    pb[0] = *(const uint4*)(Bp);
    pb[1] = *(const uint4*)(Bp + 8);

    const int iters = K / BK;
    for (int it = 0; it < iters; it++) {
        __half* buf = dsm + (it & 1) * GBUF_ELEMS;
        __half* sA = buf;
        __half* sB = buf + ABUF;
        {   // stage prefetched tile
            uint2* d; const uint2* s;
            d = (uint2*)&sA[ar * A_STR + ac];        s = (const uint2*)&pa[0]; d[0]=s[0]; d[1]=s[1];
            d = (uint2*)&sA[(ar + 64) * A_STR + ac]; s = (const uint2*)&pa[1]; d[0]=s[0]; d[1]=s[1];
            d = (uint2*)&sB[br * B_STR + bc];        s = (const uint2*)&pb[0]; d[0]=s[0]; d[1]=s[1];
            d = (uint2*)&sB[br * B_STR + bc + 8];    s = (const uint2*)&pb[1]; d[0]=s[0]; d[1]=s[1];
        }
        __syncthreads();

        if (it + 1 < iters) {   // prefetch next tile (overlaps with MMAs)
            const size_t ka = (size_t)(it + 1) * BK;
            pa[0] = *(const uint4*)(Ap + ka);
            pa[1] = *(const uint4*)(Ap + (size_t)64 * K + ka);
            const size_t kb = ka * N;
            pb[0] = *(const uint4*)(Bp + kb);
            pb[1] = *(const uint4*)(Bp + kb + 8);
        }

        #pragma unroll
        for (int kk = 0; kk < 2; kk++) {
            uint32_t a[4][4], b[4][2];
            const int arow = wm * 64 + (lane & 15);
            const int acol = kk * 16 + (lane >> 4) * 8;
            #pragma unroll
            for (int mt = 0; mt < 4; mt++)
                ldsm4(cvta_smem(&sA[(arow + mt * 16) * A_STR + acol]),
                      a[mt][0], a[mt][1], a[mt][2], a[mt][3]);
            const int brow = kk * 16 + (lane & 15);
            #pragma unroll
            for (int ng = 0; ng < 2; ng++) {
                const int bcol = wn * 32 + ng * 16 + (lane >> 4) * 8;
                ldsm4t(cvta_smem(&sB[brow * B_STR + bcol]),
                       b[2*ng][0], b[2*ng][1], b[2*ng+1][0], b[2*ng+1][1]);
            }
            #pragma unroll
            for (int mt = 0; mt < 4; mt++)
                #pragma unroll
                for (int nt = 0; nt < 4; nt++)
                    mma_fp16(acc[mt][nt], a[mt], b[nt]);
        }
        // next iter stores to the other buffer; top-of-iter sync orders it.
    }

    const int r0 = lane >> 2;
    const int cp = (lane & 3) * 2;
    #pragma unroll
    for (int mt = 0; mt < 4; mt++) {
        #pragma unroll
        for (int nt = 0; nt < 4; nt++) {
            const int gc = bn0 + wn * 32 + nt * 8 + cp;
            const float2 bv = *(const float2*)(bias + gc);
            #pragma unroll
            for (int h = 0; h < 2; h++) {
                const int gr = bm0 + wm * 64 + mt * 16 + r0 + h * 8;
                float ox = acc[mt][nt][2 * h + 0] + bv.x;
                float oy = acc[mt][nt][2 * h + 1] + bv.y;
                if (HALF_OUT) {
                    *(uint32_t*)(Ch + (size_t)gr * N + gc) = pack_h2(ox, oy);
                } else {
                    if (RESID) {
                        float2 rv = *(const float2*)(res + (size_t)gr * N + gc);
                        ox += rv.x; oy += rv.y;
                    }
                    float2 o; o.x = ox; o.y = oy;
                    *(float2*)(C + (size_t)gr * N + gc) = o;
                }
            }
        }
    }
}

// ---------------------------------------------------------------------------
// Tensor-core causal flash attention (fp16 single-MMA), double-buffered K/V.
// Grid (S/128, H, B), 256 thr (8 warps), each warp owns 16 query rows.
// ---------------------------------------------------------------------------
#define QTILE 128
#define KTILE 64
#define SROW 72
#define KVBUF (2 * KTILE * SROW)          // 9216 elems = 18,432 B / buffer
#define ASMEM_BYTES (2 * KVBUF * 2)       // 36,864 B

__global__ __launch_bounds__(256) void attn_mma(
    const __half* __restrict__ qkv, __half* __restrict__ outh)
{
    extern __shared__ __align__(16) __half dsm[];

    const int tid  = threadIdx.x;
    const int lane = tid & 31;
    const int warp = tid >> 5;
    const int qt = blockIdx.x;
    const int h  = blockIdx.y;
    const int bz = blockIdx.z;

    const size_t rowstride = QKV_N;
    const size_t batch_row = (size_t)bz * SLEN;

    // ---- stage Q tile (128 x 64) and grab fragments ----
    {
        __half* sQ = dsm;
        for (int i = tid; i < QTILE * 16; i += 256) {
            const int r = i >> 4;
            const int c = (i & 15) * 4;
            const size_t g = (batch_row + qt * QTILE + r) * rowstride + h * HDIM + c;
            *(uint2*)&sQ[r * SROW + c] = *(const uint2*)(qkv + g);
        }
    }
    __syncthreads();

    uint32_t qf[4][4];
    {
        __half* sQ = dsm;
        const int arow = warp * 16 + (lane & 15);
        #pragma unroll
        for (int ks = 0; ks < 4; ks++) {
            const int acol = ks * 16 + (lane >> 4) * 8;
            ldsm4(cvta_smem(&sQ[arow * SROW + acol]),
                  qf[ks][0], qf[ks][1], qf[ks][2], qf[ks][3]);
        }
    }
    __syncthreads();   // before K/V staging overwrites the Q region

    const int base = qt * QTILE + warp * 16;
    const int ktmax_warp = 2 * qt + (warp >= 4 ? 1 : 0);
    const int nkt = 2 * qt + 2;

    uint2 pk[4], pv[4];
    int pr[4], pc[4];
    #pragma unroll
    for (int j = 0; j < 4; j++) {
        const int i = tid + j * 256;
        pr[j] = i >> 4;
        pc[j] = (i & 15) * 4;
    }

    auto prefetch = [&](int kt) {
        #pragma unroll
        for (int j = 0; j < 4; j++) {
            const size_t gk = (batch_row + kt * KTILE + pr[j]) * rowstride
                              + DMODEL + h * HDIM + pc[j];
            pk[j] = *(const uint2*)(qkv + gk);
            pv[j] = *(const uint2*)(qkv + gk + DMODEL);
        }
    };
    auto stash = [&](__half* b) {
        __half* sK = b;
        __half* sV = b + KTILE * SROW;
        #pragma unroll
        for (int j = 0; j < 4; j++) {
            const int o = pr[j] * SROW + pc[j];
            *(uint2*)&sK[o] = pk[j];
            *(uint2*)&sV[o] = pv[j];
        }
    };

    float o[8][4];
    #pragma unroll
    for (int nt = 0; nt < 8; nt++)
        #pragma unroll
        for (int e = 0; e < 4; e++) o[nt][e] = 0.0f;
    float m_a = -1e30f, m_b = -1e30f, l_a = 0.0f, l_b = 0.0f;

    prefetch(0);
    stash(dsm);
    __syncthreads();

    for (int kt = 0; kt < nkt; kt++) {
        __half* buf = dsm + (kt & 1) * KVBUF;
        __half* sK = buf;
        __half* sV = buf + KTILE * SROW;

        if (kt + 1 < nkt) prefetch(kt + 1);

        if (kt <= ktmax_warp) {
            float s[8][4];
            #pragma unroll
            for (int nt = 0; nt < 8; nt++)
                #pragma unroll
                for (int e = 0; e < 4; e++) s[nt][e] = 0.0f;

            #pragma unroll
            for (int ks = 0; ks < 4; ks++) {
                #pragma unroll
                for (int np = 0; np < 4; np++) {
                    uint32_t k0, k1, k2, k3;
                    const int addr = (np * 16 + (lane & 15)) * SROW
                                     + ks * 16 + (lane >> 4) * 8;
                    ldsm4(cvta_smem(&sK[addr]), k0, k1, k2, k3);
                    uint32_t be[2] = {k0, k2}, bo[2] = {k1, k3};
                    mma_fp16(s[2*np],   qf[ks], be);
                    mma_fp16(s[2*np+1], qf[ks], bo);
                }
            }

            if (kt * KTILE + 63 > base) {
                const int ra = base + (lane >> 2);
                #pragma unroll
                for (int nt = 0; nt < 8; nt++) {
                    const int kc = kt * KTILE + nt * 8 + (lane & 3) * 2;
                    if (kc > ra)      s[nt][0] = -1e30f;
                    if (kc + 1 > ra)  s[nt][1] = -1e30f;
                    if (kc > ra + 8)     s[nt][2] = -1e30f;
                    if (kc + 1 > ra + 8) s[nt][3] = -1e30f;
                }
            }

            float ta = -1e30f, tb = -1e30f;
            #pragma unroll
            for (int nt = 0; nt < 8; nt++) {
                ta = fmaxf(ta, fmaxf(s[nt][0], s[nt][1]));
                tb = fmaxf(tb, fmaxf(s[nt][2], s[nt][3]));
            }
            ta = fmaxf(ta, __shfl_xor_sync(0xffffffffu, ta, 1));
            ta = fmaxf(ta, __shfl_xor_sync(0xffffffffu, ta, 2));
            tb = fmaxf(tb, __shfl_xor_sync(0xffffffffu, tb, 1));
            tb = fmaxf(tb, __shfl_xor_sync(0xffffffffu, tb, 2));

            const float mna = fmaxf(m_a, ta);
            const float mnb = fmaxf(m_b, tb);
            const float ca = __expf((m_a - mna) * SM_SCALE);
            const float cb = __expf((m_b - mnb) * SM_SCALE);
            m_a = mna; m_b = mnb;
            l_a *= ca; l_b *= cb;
            #pragma unroll
            for (int nt = 0; nt < 8; nt++) {
                o[nt][0] *= ca; o[nt][1] *= ca;
                o[nt][2] *= cb; o[nt][3] *= cb;
            }

            float sa = 0.0f, sb = 0.0f;
            #pragma unroll
            for (int nt = 0; nt < 8; nt++) {
                float p0 = __expf((s[nt][0] - mna) * SM_SCALE);
                float p1 = __expf((s[nt][1] - mna) * SM_SCALE);
                float p2 = __expf((s[nt][2] - mnb) * SM_SCALE);
                float p3 = __expf((s[nt][3] - mnb) * SM_SCALE);
                s[nt][0] = p0; s[nt][1] = p1; s[nt][2] = p2; s[nt][3] = p3;
                sa += p0 + p1; sb += p2 + p3;
            }
            sa += __shfl_xor_sync(0xffffffffu, sa, 1);
            sa += __shfl_xor_sync(0xffffffffu, sa, 2);
            sb += __shfl_xor_sync(0xffffffffu, sb, 1);
            sb += __shfl_xor_sync(0xffffffffu, sb, 2);
            l_a += sa; l_b += sb;

            #pragma unroll
            for (int ks = 0; ks < 4; ks++) {
                uint32_t pa[4];
                pa[0] = pack_h2(s[2*ks][0],   s[2*ks][1]);
                pa[1] = pack_h2(s[2*ks][2],   s[2*ks][3]);
                pa[2] = pack_h2(s[2*ks+1][0], s[2*ks+1][1]);
                pa[3] = pack_h2(s[2*ks+1][2], s[2*ks+1][3]);
                #pragma unroll
                for (int np = 0; np < 4; np++) {
                    uint32_t v0, v1, v2, v3;
                    const int addr = (ks * 16 + (lane & 15)) * SROW
                                     + np * 16 + (lane >> 4) * 8;
                    ldsm4t(cvta_smem(&sV[addr]), v0, v1, v2, v3);
                    uint32_t ve[2] = {v0, v1}, vo[2] = {v2, v3};
                    mma_fp16(o[2*np],   pa, ve);
                    mma_fp16(o[2*np+1], pa, vo);
                }
            }
        }

        if (kt + 1 < nkt) stash(dsm + ((kt + 1) & 1) * KVBUF);
        __syncthreads();
    }

    const float ia = 1.0f / l_a;
    const float ib = 1.0f / l_b;
    const int ra = base + (lane >> 2);
    const size_t rowa = (batch_row + ra) * (size_t)DMODEL + h * HDIM;
    const size_t rowb = rowa + 8 * DMODEL;
    #pragma unroll
    for (int nt = 0; nt < 8; nt++) {
        const int col = nt * 8 + (lane & 3) * 2;
        *(uint32_t*)(outh + rowa + col) = pack_h2(o[nt][0] * ia, o[nt][1] * ia);
        *(uint32_t*)(outh + rowb + col) = pack_h2(o[nt][2] * ib, o[nt][3] * ib);
    }
}

// ---------------------------------------------------------------------------
// LayerNorm over last dim, in-place. One block (256 thr) per row of 1024.
// ---------------------------------------------------------------------------
__global__ __launch_bounds__(256) void ln_kernel(
    float* __restrict__ io, const float* __restrict__ gamma,
    const float* __restrict__ beta)
{
    const int row = blockIdx.x;
    const int tid = threadIdx.x;
    float4* p = (float4*)(io + (size_t)row * DMODEL);
    float4 v = p[tid];

    float s  = v.x + v.y + v.z + v.w;
    float s2 = fmaf(v.x, v.x, fmaf(v.y, v.y, fmaf(v.z, v.z, v.w * v.w)));

    #pragma unroll
    for (int ofs = 16; ofs; ofs >>= 1) {
        s  += __shfl_xor_sync(0xffffffffu, s, ofs);
        s2 += __shfl_xor_sync(0xffffffffu, s2, ofs);
    }
    __shared__ float shs[8], shs2[8];
    const int w = tid >> 5, l = tid & 31;
    if (l == 0) { shs[w] = s; shs2[w] = s2; }
    __syncthreads();
    if (tid < 32) {
        float a  = (l < 8) ? shs[l]  : 0.0f;
        float a2 = (l < 8) ? shs2[l] : 0.0f;
        #pragma unroll
        for (int ofs = 4; ofs; ofs >>= 1) {
            a  += __shfl_xor_sync(0xffffffffu, a, ofs);
            a2 += __shfl_xor_sync(0xffffffffu, a2, ofs);
        }
        if (l == 0) { shs[0] = a; shs2[0] = a2; }
    }
    __syncthreads();

    const float mean = shs[0] * (1.0f / DMODEL);
    const float var  = shs2[0] * (1.0f / DMODEL) - mean * mean;
    const float rstd = rsqrtf(var + LN_EPS);

    float4 g  = ((const float4*)gamma)[tid];
    float4 be = ((const float4*)beta)[tid];
    float4 r;
    r.x = (v.x - mean) * rstd * g.x + be.x;
    r.y = (v.y - mean) * rstd * g.y + be.y;
    r.z = (v.z - mean) * rstd * g.z + be.z;
    r.w = (v.w - mean) * rstd * g.w + be.w;
    p[tid] = r;
}

// ---------------------------------------------------------------------------
extern "C" void kernel_launch(void* const* d_in, const int* in_sizes, int n_in,
                              void* d_out, int out_size)
{
    const float* x     = (const float*)d_in[0];
    const float* Wqkv  = (const float*)d_in[1];
    const float* bqkv  = (const float*)d_in[2];
    const float* Wout  = (const float*)d_in[3];
    const float* bout  = (const float*)d_in[4];
    const float* gamma = (const float*)d_in[5];
    const float* beta  = (const float*)d_in[6];
    float* out = (float*)d_out;

    __half *xh, *wq, *wo, *qkv, *attn;
    cudaGetSymbolAddress((void**)&xh,   g_xh);
    cudaGetSymbolAddress((void**)&wq,   g_wqkv);
    cudaGetSymbolAddress((void**)&wo,   g_wout);
    cudaGetSymbolAddress((void**)&qkv,  g_qkv);
    cudaGetSymbolAddress((void**)&attn, g_attn);

    static bool attrs_set = false;
    if (!attrs_set) {
        cudaFuncSetAttribute(mma_gemm<false, true>,
                             cudaFuncAttributeMaxDynamicSharedMemorySize, GSMEM_BYTES);
        cudaFuncSetAttribute(mma_gemm<true, false>,
                             cudaFuncAttributeMaxDynamicSharedMemorySize, GSMEM_BYTES);
        cudaFuncSetAttribute(attn_mma,
                             cudaFuncAttributeMaxDynamicSharedMemorySize, ASMEM_BYTES);
        attrs_set = true;
    }

    // 0) fp32 -> fp16 conversions
    {
        int n4 = MROWS * DMODEL / 4;
        cvt_kernel<<<(n4 + 255) / 256, 256>>>((const float4*)x, (uint2*)xh, n4);
        n4 = DMODEL * QKV_N / 4;
        cvt_kernel<<<(n4 + 255) / 256, 256>>>((const float4*)Wqkv, (uint2*)wq, n4);
        n4 = DMODEL * DMODEL / 4;
        cvt_kernel<<<(n4 + 255) / 256, 256>>>((const float4*)Wout, (uint2*)wo, n4);
    }
    // 1) QKV projection -> fp16 output
    {
        dim3 grid(QKV_N / BN, MROWS / BM);
        mma_gemm<false, true><<<grid, 256, GSMEM_BYTES>>>(
            xh, wq, bqkv, nullptr, nullptr, qkv, MROWS, QKV_N, DMODEL);
    }
    // 2) tensor-core causal flash attention -> fp16 output
    {
        dim3 grid(SLEN / QTILE, NHEADS, BATCH);
        attn_mma<<<grid, 256, ASMEM_BYTES>>>(qkv, attn);
    }
    // 3) out projection + bias + residual -> fp32
    {
        dim3 grid(DMODEL / BN, MROWS / BM);
        mma_gemm<true, false><<<grid, 256, GSMEM_BYTES>>>(
            attn, wo, bout, x, out, nullptr, MROWS, DMODEL, DMODEL);
    }
    // 4) LayerNorm in-place on d_out
    ln_kernel<<<MROWS, 256>>>(out, gamma, beta);
}